// round 12
// baseline (speedup 1.0000x reference)
#include <cuda_runtime.h>
#include <cstdint>
#include <cstddef>

// ---------------------------------------------------------------------------
// Problem constants
// ---------------------------------------------------------------------------
constexpr int B    = 2048;
constexpr int S    = 24;
constexpr int T    = 25;
constexpr int H    = 256;
constexpr int E    = 300;
constexpr int VIN  = 64;
constexpr int VOUT = 128;
constexpr int G3   = 768;   // 3*H
constexpr int H2   = 512;   // 2*H

// ---------------------------------------------------------------------------
// Device scratch
// ---------------------------------------------------------------------------
__device__ float g_emb_gi_f[VIN * G3];
__device__ float g_emb_gi_b[VIN * G3];
__device__ float g_dec_gi_emb[VOUT * G3];
__device__ float g_dec_logit_emb[VOUT * VOUT];
__device__ float g_bias_cat[1024];
__device__ float g_hf[B * H];
__device__ float g_hb[B * H];
__device__ float g_h[B * H];
__device__ float g_cat512[B * H2];
__device__ float g_enc_out[(size_t)B * S * H2];
__device__ float g_enc_proj[(size_t)B * S * H];
__device__ float g_gh[2 * B * G3];
__device__ float g_g1[B * 1024];
__device__ float g_gi[B * G3];
__device__ float g_weighted[B * H2];
__device__ float g_xcat[B * G3];
// transposed weights [N, K] row-major (tf32-rounded)
__device__ float g_WhhT_f[G3 * H];
__device__ float g_WhhT_b[G3 * H];
__device__ float g_WcatT[1024 * H];
__device__ float g_dec_WihT[G3 * H2];
__device__ float g_fcWT[VOUT * G3];
__device__ float g_enc_fcWT[H * H2];
__device__ float g_attn_WeT[H * H2];

// ---------------------------------------------------------------------------
// Activations / conversion
// ---------------------------------------------------------------------------
__device__ __forceinline__ float tanh_approx(float x) {
    float y; asm("tanh.approx.f32 %0, %1;" : "=f"(y) : "f"(x)); return y;
}
__device__ __forceinline__ float tanh_acc(float x) {
    float ax = fabsf(x);
    float t  = __expf(-2.0f * ax);
    float r  = __fdividef(1.0f - t, 1.0f + t);
    return copysignf(r, x);
}
__device__ __forceinline__ float sig_acc(float x) {
    return __fdividef(1.0f, 1.0f + __expf(-x));
}
// round fp32 -> tf32 (RNA), returned as float with low mantissa bits zero
__device__ __forceinline__ float rnd_tf32(float x) {
    uint32_t r; asm("cvt.rna.tf32.f32 %0, %1;" : "=r"(r) : "f"(x));
    return __uint_as_float(r);
}
__device__ __forceinline__ void cp_async16(uint32_t saddr, const void* g) {
    asm volatile("cp.async.ca.shared.global [%0], [%1], 16;"
                 :: "r"(saddr), "l"(g) : "memory");
}
__device__ __forceinline__ uint32_t smem_u32(const void* p) {
    uint32_t a;
    asm("{ .reg .u64 t; cvta.to.shared.u64 t, %1; cvt.u32.u64 %0, t; }" : "=r"(a) : "l"(p));
    return a;
}

// ---------------------------------------------------------------------------
// Precompute tables: 4 small GEMMs (K=300) fused into one launch
// (outputs feed elementwise consumers / epilogue adds only — no tf32 rounding)
// ---------------------------------------------------------------------------
__global__ void tables_k(const float* __restrict__ enc_emb,
                         const float* __restrict__ dec_emb,
                         const float* __restrict__ Wih_f, const float* __restrict__ bih_f,
                         const float* __restrict__ Wih_b, const float* __restrict__ bih_b,
                         const float* __restrict__ dWih,  const float* __restrict__ dbih,
                         const float* __restrict__ fcW_emb, const float* __restrict__ fcb,
                         float* __restrict__ o0, float* __restrict__ o1,
                         float* __restrict__ o2, float* __restrict__ o3) {
    int idx = blockIdx.x * blockDim.x + threadIdx.x;
    const int J0 = VIN * G3, J1 = 2 * VIN * G3, J2 = J1 + VOUT * G3, J3 = J2 + VOUT * VOUT;
    if (idx >= J3) return;
    const float* A; const float* Bw; const float* bias; float* C;
    int m, n, ldb;
    if (idx < J0)      { int r = idx;      m = r / G3;  n = r % G3;  A = enc_emb; Bw = Wih_f;   bias = bih_f; C = o0 + r; ldb = G3; }
    else if (idx < J1) { int r = idx - J0; m = r / G3;  n = r % G3;  A = enc_emb; Bw = Wih_b;   bias = bih_b; C = o1 + r; ldb = G3; }
    else if (idx < J2) { int r = idx - J1; m = r / G3;  n = r % G3;  A = dec_emb; Bw = dWih;    bias = dbih;  C = o2 + r; ldb = G3; }
    else               { int r = idx - J2; m = r / VOUT; n = r % VOUT; A = dec_emb; Bw = fcW_emb; bias = fcb; C = o3 + r; ldb = VOUT; }
    float s = bias[n];
    const float* Ar = A + (size_t)m * E;
#pragma unroll 4
    for (int k = 0; k < E; k++) s = fmaf(Ar[k], Bw[(size_t)k * ldb + n], s);
    *C = s;
}

// ---------------------------------------------------------------------------
// Fused weight preparation: 6 transposes + bias_cat, all tf32-rounded
// ---------------------------------------------------------------------------
__global__ void prep_k(const float* __restrict__ Whh_f, const float* __restrict__ Whh_b,
                       const float* __restrict__ dWih300,
                       const float* __restrict__ fcW,
                       const float* __restrict__ enc_fcW, const float* __restrict__ attn_We,
                       const float* __restrict__ attn_b, const float* __restrict__ dec_bhh,
                       float* __restrict__ WhhT_f, float* __restrict__ WhhT_b,
                       float* __restrict__ dec_WihT, float* __restrict__ fcWT,
                       float* __restrict__ enc_fcWT, float* __restrict__ attn_WeT,
                       float* __restrict__ bias_cat) {
    int idx = blockIdx.x * blockDim.x + threadIdx.x;
    const int L0 = 256 * 768;
    const int L1 = L0 + 256 * 768;
    const int L2 = L1 + 512 * 768;
    const int L3 = L2 + 768 * 128;
    const int L4 = L3 + 512 * 256;
    const int L5 = L4 + 512 * 256;
    const int L6 = L5 + 1024;
    if (idx >= L6) return;
    if (idx < L0)      { int li = idx;      int r = li / 768, c = li % 768; WhhT_f[(size_t)c * 256 + r] = rnd_tf32(Whh_f[li]); }
    else if (idx < L1) { int li = idx - L0; int r = li / 768, c = li % 768; WhhT_b[(size_t)c * 256 + r] = rnd_tf32(Whh_b[li]); }
    else if (idx < L2) { int li = idx - L1; int r = li / 768, c = li % 768; dec_WihT[(size_t)c * 512 + r] = rnd_tf32(dWih300[li]); }
    else if (idx < L3) { int li = idx - L2; int r = li / 128, c = li % 128; fcWT[(size_t)c * 768 + r] = rnd_tf32(fcW[li]); }
    else if (idx < L4) { int li = idx - L3; int r = li / 256, c = li % 256; enc_fcWT[(size_t)c * 512 + r] = rnd_tf32(enc_fcW[li]); }
    else if (idx < L5) { int li = idx - L4; int r = li / 256, c = li % 256; attn_WeT[(size_t)c * 512 + r] = rnd_tf32(attn_We[li]); }
    else               { int li = idx - L5; bias_cat[li] = (li < H) ? attn_b[li] : dec_bhh[li - H]; }
}

__global__ void build_wcatT(const float* __restrict__ Wh, const float* __restrict__ Whh,
                            float* __restrict__ WcatT) {
    int idx = blockIdx.x * blockDim.x + threadIdx.x;
    if (idx >= 1024 * H) return;
    int n = idx / H, k = idx % H;
    WcatT[idx] = rnd_tf32((n < H) ? Wh[(size_t)k * H + n] : Whh[(size_t)k * G3 + (n - H)]);
}

// ---------------------------------------------------------------------------
// Tensor-core tf32 GEMM, mma.sync m16n8k8 + cp.async 2-stage pipeline.
// Operands must be pre-rounded to tf32 by producers (cp.async copies raw).
// Warp grid WM x WN, warp tile (MT*16) x (NT*8), CTA tile BM x BN, BK=32.
// Smem rows stride 36 floats. blockIdx.z==1 -> second problem.
// ---------------------------------------------------------------------------
template<int WM, int WN, int MT, int NT>
__global__ __launch_bounds__(256, 2)
void gemm_mma(const float* __restrict__ A, int lda,
              const float* __restrict__ Bt,            // [N,K] row-major
              float* __restrict__ C, int ldc,
              int M, int N, int K,
              const float* __restrict__ bias,
              const float* __restrict__ gtab, const int* __restrict__ gidx, int ldgt,
              int act,
              const float* __restrict__ A2, const float* __restrict__ Bt2,
              float* __restrict__ C2, const float* __restrict__ bias2) {
    constexpr int BM  = WM * MT * 16;
    constexpr int BN  = WN * NT * 8;
    constexpr int LA  = BM * 8 / 256;   // float4 cp.async per thread (A)
    constexpr int LB  = BN * 8 / 256;   // float4 cp.async per thread (B)
    constexpr int STG = (BM + BN) * 36; // floats per stage

    if (blockIdx.z == 1) { A = A2; Bt = Bt2; C = C2; bias = bias2; }

    extern __shared__ float sm[];
    const uint32_t sbase = smem_u32(sm);

    const int tid  = threadIdx.x;
    const int lane = tid & 31;
    const int wid  = tid >> 5;
    const int wm   = wid % WM;
    const int wn   = wid / WM;
    const int grp  = lane >> 2;
    const int tig  = lane & 3;
    const int m0   = blockIdx.y * BM;
    const int n0   = blockIdx.x * BN;

    const int arow = tid >> 3;          // 0..31 (x8 rounds below)
    const int k4   = (tid & 7) * 4;     // k offset within 32-chunk

    auto prefetch = [&](int k0, int st) {
        const uint32_t base = sbase + (uint32_t)st * STG * 4;
#pragma unroll
        for (int l = 0; l < LA; l++) {
            int row = arow + l * 32;
            cp_async16(base + (row * 36 + k4) * 4,
                       A + (size_t)(m0 + row) * lda + k0 + k4);
        }
#pragma unroll
        for (int l = 0; l < LB; l++) {
            int row = arow + l * 32;
            cp_async16(base + ((BM + row) * 36 + k4) * 4,
                       Bt + (size_t)(n0 + row) * K + k0 + k4);
        }
        asm volatile("cp.async.commit_group;" ::: "memory");
    };

    float acc[MT][NT][4];
#pragma unroll
    for (int mt = 0; mt < MT; mt++)
#pragma unroll
        for (int nt = 0; nt < NT; nt++)
#pragma unroll
            for (int j = 0; j < 4; j++) acc[mt][nt][j] = 0.0f;

    const int nk = K >> 5;
    prefetch(0, 0);

    for (int kc = 0; kc < nk; kc++) {
        const int cur = kc & 1;
        if (kc + 1 < nk) {
            prefetch((kc + 1) * 32, cur ^ 1);
            asm volatile("cp.async.wait_group 1;" ::: "memory");
        } else {
            asm volatile("cp.async.wait_group 0;" ::: "memory");
        }
        __syncthreads();

        const float* As = sm + cur * STG;
        const float* Bs = As + BM * 36;

#pragma unroll
        for (int ks = 0; ks < 4; ks++) {
            const int kb = ks * 8;
            uint32_t af[MT][4], bf[NT][2];
#pragma unroll
            for (int mt = 0; mt < MT; mt++) {
                const int r = wm * MT * 16 + mt * 16 + grp;
                af[mt][0] = __float_as_uint(As[(r    ) * 36 + kb + tig]);
                af[mt][1] = __float_as_uint(As[(r + 8) * 36 + kb + tig]);
                af[mt][2] = __float_as_uint(As[(r    ) * 36 + kb + tig + 4]);
                af[mt][3] = __float_as_uint(As[(r + 8) * 36 + kb + tig + 4]);
            }
#pragma unroll
            for (int nt = 0; nt < NT; nt++) {
                const int c_ = wn * NT * 8 + nt * 8 + grp;
                bf[nt][0] = __float_as_uint(Bs[c_ * 36 + kb + tig]);
                bf[nt][1] = __float_as_uint(Bs[c_ * 36 + kb + tig + 4]);
            }
#pragma unroll
            for (int mt = 0; mt < MT; mt++)
#pragma unroll
                for (int nt = 0; nt < NT; nt++)
                    asm volatile(
                        "mma.sync.aligned.m16n8k8.row.col.f32.tf32.tf32.f32 "
                        "{%0,%1,%2,%3}, {%4,%5,%6,%7}, {%8,%9}, {%0,%1,%2,%3};"
                        : "+f"(acc[mt][nt][0]), "+f"(acc[mt][nt][1]),
                          "+f"(acc[mt][nt][2]), "+f"(acc[mt][nt][3])
                        : "r"(af[mt][0]), "r"(af[mt][1]), "r"(af[mt][2]), "r"(af[mt][3]),
                          "r"(bf[nt][0]), "r"(bf[nt][1]));
        }
        __syncthreads();
    }

    // epilogue
#pragma unroll
    for (int mt = 0; mt < MT; mt++) {
        const int r0 = m0 + wm * MT * 16 + mt * 16 + grp;
        const int r1 = r0 + 8;
        const float* gr0 = gtab ? (gtab + (size_t)gidx[r0] * ldgt) : nullptr;
        const float* gr1 = gtab ? (gtab + (size_t)gidx[r1] * ldgt) : nullptr;
        float* C0 = C + (size_t)r0 * ldc;
        float* C1 = C + (size_t)r1 * ldc;
#pragma unroll
        for (int nt = 0; nt < NT; nt++) {
            const int n = n0 + wn * NT * 8 + nt * 8 + 2 * tig;
            float v0 = acc[mt][nt][0], v1 = acc[mt][nt][1];
            float v2 = acc[mt][nt][2], v3 = acc[mt][nt][3];
            if (bias) { float b0 = bias[n], b1 = bias[n + 1]; v0 += b0; v1 += b1; v2 += b0; v3 += b1; }
            if (gr0)  { v0 += gr0[n]; v1 += gr0[n + 1]; v2 += gr1[n]; v3 += gr1[n + 1]; }
            if (act == 1) {   // tanh + tf32-round (output feeds a GEMM A operand)
                v0 = rnd_tf32(tanh_acc(v0)); v1 = rnd_tf32(tanh_acc(v1));
                v2 = rnd_tf32(tanh_acc(v2)); v3 = rnd_tf32(tanh_acc(v3));
            }
            *reinterpret_cast<float2*>(C0 + n) = make_float2(v0, v1);
            *reinterpret_cast<float2*>(C1 + n) = make_float2(v2, v3);
        }
    }
}

// ---------------------------------------------------------------------------
// Encoder GRU cell (both directions via blockIdx.z); h written tf32-rounded
// ---------------------------------------------------------------------------
__global__ void enc_cell(const float* __restrict__ gh_f, const float* __restrict__ gh_b,
                         const float* __restrict__ emb_f, const float* __restrict__ emb_b,
                         const int* __restrict__ src, int s,
                         float* __restrict__ hf, float* __restrict__ hb,
                         float* __restrict__ enc_out) {
    int dir = blockIdx.z;
    int idx = blockIdx.x * blockDim.x + threadIdx.x;
    int b = idx >> 8;
    int h = idx & 255;
    int s_in = dir ? (S - 1 - s) : s;
    int tok  = src[s_in * B + b];
    const float* gh = (dir ? gh_b : gh_f) + (size_t)b * G3;
    const float* gi = (dir ? emb_b : emb_f) + (size_t)tok * G3;
    float* hp = (dir ? hb : hf) + (size_t)b * H + h;
    float r = sig_acc(gi[h] + gh[h]);
    float z = sig_acc(gi[H + h] + gh[H + h]);
    float n = tanh_acc(gi[2 * H + h] + r * gh[2 * H + h]);
    float hprev = *hp;
    float hn = rnd_tf32((1.0f - z) * n + z * hprev);
    *hp = hn;
    enc_out[((size_t)b * S + s_in) * H2 + dir * H + h] = hn;
}

// ---------------------------------------------------------------------------
// Decoder GRU cell; h/xcat written tf32-rounded
// ---------------------------------------------------------------------------
__global__ void dec_cell(const float* __restrict__ g1, const float* __restrict__ gi,
                         float* __restrict__ h, float* __restrict__ xcat) {
    int idx = blockIdx.x * blockDim.x + threadIdx.x;
    int b = idx >> 8;
    int hh = idx & 255;
    const float* gh  = g1 + (size_t)b * 1024 + H;
    const float* gip = gi + (size_t)b * G3;
    float r = sig_acc(gip[hh] + gh[hh]);
    float z = sig_acc(gip[H + hh] + gh[H + hh]);
    float n = tanh_acc(gip[2 * H + hh] + r * gh[2 * H + hh]);
    float hprev = h[(size_t)b * H + hh];
    float hn = rnd_tf32((1.0f - z) * n + z * hprev);
    h[(size_t)b * H + hh] = hn;
    xcat[(size_t)b * G3 + hh] = hn;
}

// ---------------------------------------------------------------------------
// Attention: parallel energies (warp-per-s); weighted written tf32-rounded
// ---------------------------------------------------------------------------
__global__ __launch_bounds__(256)
void attn_k(const float* __restrict__ g1, const float* __restrict__ proj,
            const float* __restrict__ enc_out, const float* __restrict__ v,
            float* __restrict__ weighted, float* __restrict__ xcat) {
    const int b   = blockIdx.x;
    const int tid = threadIdx.x;
    const int wid = tid >> 5, lane = tid & 31;
    __shared__ float q_sh[256], v_sh[256], e_sh[S], a_sh[S];

    q_sh[tid] = g1[(size_t)b * 1024 + tid];
    v_sh[tid] = v[tid];
    __syncthreads();

    const float* prow = proj + (size_t)b * S * H;
#pragma unroll
    for (int r = 0; r < 3; r++) {
        const int s = wid + r * 8;
        const float4* p4 = reinterpret_cast<const float4*>(prow + s * H + lane * 8);
        float4 p0 = p4[0], p1 = p4[1];
        float4 q0 = *reinterpret_cast<const float4*>(&q_sh[lane * 8]);
        float4 q1 = *reinterpret_cast<const float4*>(&q_sh[lane * 8 + 4]);
        float4 w0 = *reinterpret_cast<const float4*>(&v_sh[lane * 8]);
        float4 w1 = *reinterpret_cast<const float4*>(&v_sh[lane * 8 + 4]);
        float val = w0.x * tanh_approx(q0.x + p0.x)
                  + w0.y * tanh_approx(q0.y + p0.y)
                  + w0.z * tanh_approx(q0.z + p0.z)
                  + w0.w * tanh_approx(q0.w + p0.w)
                  + w1.x * tanh_approx(q1.x + p1.x)
                  + w1.y * tanh_approx(q1.y + p1.y)
                  + w1.z * tanh_approx(q1.z + p1.z)
                  + w1.w * tanh_approx(q1.w + p1.w);
#pragma unroll
        for (int o = 16; o > 0; o >>= 1) val += __shfl_xor_sync(0xffffffffu, val, o);
        if (lane == 0) e_sh[s] = val;
    }
    __syncthreads();

    if (tid < 32) {
        float x = (tid < S) ? e_sh[tid] : -1e30f;
        float mx = x;
#pragma unroll
        for (int o = 16; o > 0; o >>= 1) mx = fmaxf(mx, __shfl_xor_sync(0xffffffffu, mx, o));
        float ex = (tid < S) ? __expf(x - mx) : 0.0f;
        float sm = ex;
#pragma unroll
        for (int o = 16; o > 0; o >>= 1) sm += __shfl_xor_sync(0xffffffffu, sm, o);
        if (tid < S) a_sh[tid] = __fdividef(ex, sm);
    }
    __syncthreads();

    const float* orow = enc_out + (size_t)b * S * H2;
#pragma unroll
    for (int d = tid; d < H2; d += 256) {
        float acc = 0.0f;
#pragma unroll
        for (int s = 0; s < S; s++) acc = fmaf(a_sh[s], orow[s * H2 + d], acc);
        float av = rnd_tf32(acc);
        weighted[(size_t)b * H2 + d] = av;
        xcat[(size_t)b * G3 + H + d] = av;
    }
}

__global__ void concat_h(const float* __restrict__ hf, const float* __restrict__ hb,
                         float* __restrict__ cat) {
    int idx = blockIdx.x * blockDim.x + threadIdx.x;
    int b = idx >> 9, j = idx & 511;
    cat[idx] = (j < H) ? hf[b * H + j] : hb[b * H + (j - H)];
}

// ---------------------------------------------------------------------------
// Host launch helpers
// ---------------------------------------------------------------------------
constexpr int SMEM_MAIN = 2 * (128 + 64) * 36 * 4;   // 55296 B (BM=128,BN=64)
constexpr int SMEM_LOG  = 2 * (64 + 64) * 36 * 4;    // 36864 B (BM=64, BN=64)

static void gemm_mainL(const float* A, int lda, const float* Bt,
                       float* C, int ldc, int M, int N, int K,
                       const float* bias, const float* gtab, const int* gidx, int ldgt,
                       int act,
                       const float* A2 = nullptr, const float* Bt2 = nullptr,
                       float* C2 = nullptr, const float* bias2 = nullptr) {
    static bool attr_set = false;
    if (!attr_set) {
        cudaFuncSetAttribute(gemm_mma<4, 2, 2, 4>,
                             cudaFuncAttributeMaxDynamicSharedMemorySize, SMEM_MAIN);
        attr_set = true;
    }
    dim3 g(N / 64, M / 128, A2 ? 2 : 1);
    gemm_mma<4, 2, 2, 4><<<g, 256, SMEM_MAIN>>>(A, lda, Bt, C, ldc, M, N, K,
                                                bias, gtab, gidx, ldgt, act,
                                                A2, Bt2, C2, bias2);
}
static void gemm_logL(const float* A, int lda, const float* Bt,
                      float* C, int ldc, int M, int N, int K,
                      const float* bias, const float* gtab, const int* gidx, int ldgt,
                      int act) {
    static bool attr_set = false;
    if (!attr_set) {
        cudaFuncSetAttribute(gemm_mma<2, 4, 2, 2>,
                             cudaFuncAttributeMaxDynamicSharedMemorySize, SMEM_LOG);
        attr_set = true;
    }
    dim3 g(N / 64, M / 64, 1);
    gemm_mma<2, 4, 2, 2><<<g, 256, SMEM_LOG>>>(A, lda, Bt, C, ldc, M, N, K,
                                               bias, gtab, gidx, ldgt, act,
                                               nullptr, nullptr, nullptr, nullptr);
}

extern "C" void kernel_launch(void* const* d_in, const int* in_sizes, int n_in,
                              void* d_out, int out_size) {
    const int*   src       = (const int*)  d_in[0];
    const int*   trg       = (const int*)  d_in[1];
    const float* enc_emb   = (const float*)d_in[2];
    const float* enc_Wih_f = (const float*)d_in[3];
    const float* enc_Whh_f = (const float*)d_in[4];
    const float* enc_bih_f = (const float*)d_in[5];
    const float* enc_bhh_f = (const float*)d_in[6];
    const float* enc_Wih_b = (const float*)d_in[7];
    const float* enc_Whh_b = (const float*)d_in[8];
    const float* enc_bih_b = (const float*)d_in[9];
    const float* enc_bhh_b = (const float*)d_in[10];
    const float* enc_fcW   = (const float*)d_in[11];
    const float* enc_fcb   = (const float*)d_in[12];
    const float* attn_Wh   = (const float*)d_in[13];
    const float* attn_We   = (const float*)d_in[14];
    const float* attn_b    = (const float*)d_in[15];
    const float* attn_v    = (const float*)d_in[16];
    const float* dec_emb   = (const float*)d_in[17];
    const float* dec_Wih   = (const float*)d_in[18];
    const float* dec_Whh   = (const float*)d_in[19];
    const float* dec_bih   = (const float*)d_in[20];
    const float* dec_bhh   = (const float*)d_in[21];
    const float* fcW       = (const float*)d_in[22];
    const float* fcb       = (const float*)d_in[23];
    float* out = (float*)d_out;

    float *p_emb_gi_f, *p_emb_gi_b, *p_dec_gi_emb, *p_dec_logit_emb;
    float *p_bias_cat, *p_hf, *p_hb, *p_h, *p_cat512;
    float *p_enc_out, *p_enc_proj, *p_gh, *p_g1, *p_gi, *p_weighted, *p_xcat;
    float *p_WhhT_f, *p_WhhT_b, *p_WcatT, *p_dec_WihT, *p_fcWT, *p_enc_fcWT, *p_attn_WeT;
    void* tmp;
    cudaGetSymbolAddress(&tmp, g_emb_gi_f);      p_emb_gi_f     = (float*)tmp;
    cudaGetSymbolAddress(&tmp, g_emb_gi_b);      p_emb_gi_b     = (float*)tmp;
    cudaGetSymbolAddress(&tmp, g_dec_gi_emb);    p_dec_gi_emb   = (float*)tmp;
    cudaGetSymbolAddress(&tmp, g_dec_logit_emb); p_dec_logit_emb= (float*)tmp;
    cudaGetSymbolAddress(&tmp, g_bias_cat);      p_bias_cat     = (float*)tmp;
    cudaGetSymbolAddress(&tmp, g_hf);            p_hf           = (float*)tmp;
    cudaGetSymbolAddress(&tmp, g_hb);            p_hb           = (float*)tmp;
    cudaGetSymbolAddress(&tmp, g_h);             p_h            = (float*)tmp;
    cudaGetSymbolAddress(&tmp, g_cat512);        p_cat512       = (float*)tmp;
    cudaGetSymbolAddress(&tmp, g_enc_out);       p_enc_out      = (float*)tmp;
    cudaGetSymbolAddress(&tmp, g_enc_proj);      p_enc_proj     = (float*)tmp;
    cudaGetSymbolAddress(&tmp, g_gh);            p_gh           = (float*)tmp;
    cudaGetSymbolAddress(&tmp, g_g1);            p_g1           = (float*)tmp;
    cudaGetSymbolAddress(&tmp, g_gi);            p_gi           = (float*)tmp;
    cudaGetSymbolAddress(&tmp, g_weighted);      p_weighted     = (float*)tmp;
    cudaGetSymbolAddress(&tmp, g_xcat);          p_xcat         = (float*)tmp;
    cudaGetSymbolAddress(&tmp, g_WhhT_f);        p_WhhT_f       = (float*)tmp;
    cudaGetSymbolAddress(&tmp, g_WhhT_b);        p_WhhT_b       = (float*)tmp;
    cudaGetSymbolAddress(&tmp, g_WcatT);         p_WcatT        = (float*)tmp;
    cudaGetSymbolAddress(&tmp, g_dec_WihT);      p_dec_WihT     = (float*)tmp;
    cudaGetSymbolAddress(&tmp, g_fcWT);          p_fcWT         = (float*)tmp;
    cudaGetSymbolAddress(&tmp, g_enc_fcWT);      p_enc_fcWT     = (float*)tmp;
    cudaGetSymbolAddress(&tmp, g_attn_WeT);      p_attn_WeT     = (float*)tmp;

    // ---- precompute: tables + fused weight prep ----
    {
        int total = 2 * VIN * G3 + VOUT * G3 + VOUT * VOUT;
        tables_k<<<(total + 255) / 256, 256>>>(enc_emb, dec_emb,
                                               enc_Wih_f, enc_bih_f,
                                               enc_Wih_b, enc_bih_b,
                                               dec_Wih, dec_bih,
                                               fcW + (size_t)G3 * VOUT, fcb,
                                               p_emb_gi_f, p_emb_gi_b,
                                               p_dec_gi_emb, p_dec_logit_emb);
    }
    {
        const int L6 = 2 * 256 * 768 + 512 * 768 + 768 * 128 + 2 * 512 * 256 + 1024;
        prep_k<<<(L6 + 255) / 256, 256>>>(enc_Whh_f, enc_Whh_b,
                                          dec_Wih + (size_t)E * G3, fcW,
                                          enc_fcW, attn_We, attn_b, dec_bhh,
                                          p_WhhT_f, p_WhhT_b, p_dec_WihT, p_fcWT,
                                          p_enc_fcWT, p_attn_WeT, p_bias_cat);
        build_wcatT<<<(1024 * H + 255) / 256, 256>>>(attn_Wh, dec_Whh, p_WcatT);
    }
    cudaMemsetAsync(p_hf, 0, (size_t)B * H * sizeof(float));
    cudaMemsetAsync(p_hb, 0, (size_t)B * H * sizeof(float));
    cudaMemsetAsync(out, 0, (size_t)B * VOUT * sizeof(float));

    // ---- encoder: 24 steps, fwd+bwd fused via grid.z ----
    for (int s = 0; s < S; s++) {
        gemm_mainL(p_hf, H, p_WhhT_f, p_gh, G3, B, G3, H,
                   enc_bhh_f, nullptr, nullptr, 0, 0,
                   p_hb, p_WhhT_b, p_gh + (size_t)B * G3, enc_bhh_b);
        enc_cell<<<dim3(B * H / 256, 1, 2), 256>>>(p_gh, p_gh + (size_t)B * G3,
                                                   p_emb_gi_f, p_emb_gi_b,
                                                   src, s, p_hf, p_hb, p_enc_out);
    }

    // ---- decoder init hidden = tanh([hf|hb] @ enc_fcW + enc_fcb) ----
    concat_h<<<B * H2 / 256, 256>>>(p_hf, p_hb, p_cat512);
    gemm_mainL(p_cat512, H2, p_enc_fcWT, p_h, H, B, H, H2,
               enc_fcb, nullptr, nullptr, 0, /*tanh+rnd*/1);

    // ---- enc_proj = enc_out @ attn_We ----
    gemm_mainL(p_enc_out, H2, p_attn_WeT, p_enc_proj, H, B * S, H, H2,
               nullptr, nullptr, nullptr, 0, 0);

    // ---- decoder: 24 steps ----
    for (int t = 0; t < T - 1; t++) {
        const int* tok = trg + t * B;
        gemm_mainL(p_h, H, p_WcatT, p_g1, 1024, B, 1024, H,
                   p_bias_cat, nullptr, nullptr, 0, 0);
        attn_k<<<B, 256>>>(p_g1, p_enc_proj, p_enc_out, attn_v, p_weighted, p_xcat);
        gemm_mainL(p_weighted, H2, p_dec_WihT, p_gi, G3, B, G3, H2,
                   nullptr, p_dec_gi_emb, tok, G3, 0);
        dec_cell<<<B * H / 256, 256>>>(p_g1, p_gi, p_h, p_xcat);
        gemm_logL(p_xcat, G3, p_fcWT, out + (size_t)(t + 1) * B * VOUT, VOUT,
                  B, VOUT, G3, nullptr, p_dec_logit_emb, tok, VOUT, 0);
    }
}

// round 13
// speedup vs baseline: 1.0058x; 1.0058x over previous
#include <cuda_runtime.h>
#include <cstdint>
#include <cstddef>

// ---------------------------------------------------------------------------
// Problem constants
// ---------------------------------------------------------------------------
constexpr int B    = 2048;
constexpr int S    = 24;
constexpr int T    = 25;
constexpr int H    = 256;
constexpr int E    = 300;
constexpr int VIN  = 64;
constexpr int VOUT = 128;
constexpr int G3   = 768;   // 3*H
constexpr int H2   = 512;   // 2*H

// ---------------------------------------------------------------------------
// Device scratch
// ---------------------------------------------------------------------------
__device__ float g_emb_gi_f[VIN * G3];
__device__ float g_emb_gi_b[VIN * G3];
__device__ float g_dec_gi_emb[VOUT * G3];
__device__ float g_dec_logit_emb[VOUT * VOUT];
__device__ float g_bias_cat[1024];
__device__ float g_hf[B * H];
__device__ float g_hb[B * H];
__device__ float g_h[B * H];
__device__ float g_cat512[B * H2];
__device__ float g_enc_out[(size_t)B * S * H2];
__device__ float g_enc_proj[(size_t)B * S * H];
__device__ float g_gh[2 * B * G3];
__device__ float g_g1[B * 1024];
__device__ float g_gi[B * G3];
__device__ float g_weighted[B * H2];
__device__ float g_xcat[B * G3];
// transposed weights [N, K] row-major (tf32-rounded)
__device__ float g_WhhT_f[G3 * H];
__device__ float g_WhhT_b[G3 * H];
__device__ float g_WcatT[1024 * H];
__device__ float g_dec_WihT[G3 * H2];
__device__ float g_fcWT[VOUT * G3];
__device__ float g_enc_fcWT[H * H2];
__device__ float g_attn_WeT[H * H2];

// ---------------------------------------------------------------------------
// Activations / conversion
// ---------------------------------------------------------------------------
__device__ __forceinline__ float tanh_approx(float x) {
    float y; asm("tanh.approx.f32 %0, %1;" : "=f"(y) : "f"(x)); return y;
}
__device__ __forceinline__ float tanh_acc(float x) {
    float ax = fabsf(x);
    float t  = __expf(-2.0f * ax);
    float r  = __fdividef(1.0f - t, 1.0f + t);
    return copysignf(r, x);
}
__device__ __forceinline__ float sig_acc(float x) {
    return __fdividef(1.0f, 1.0f + __expf(-x));
}
// round fp32 -> tf32 (RNA), returned as float with low mantissa bits zero
__device__ __forceinline__ float rnd_tf32(float x) {
    uint32_t r; asm("cvt.rna.tf32.f32 %0, %1;" : "=r"(r) : "f"(x));
    return __uint_as_float(r);
}
__device__ __forceinline__ void cp_async16(uint32_t saddr, const void* g) {
    asm volatile("cp.async.ca.shared.global [%0], [%1], 16;"
                 :: "r"(saddr), "l"(g) : "memory");
}
__device__ __forceinline__ uint32_t smem_u32(const void* p) {
    uint32_t a;
    asm("{ .reg .u64 t; cvta.to.shared.u64 t, %1; cvt.u32.u64 %0, t; }" : "=r"(a) : "l"(p));
    return a;
}

// ---------------------------------------------------------------------------
// Precompute tables: 4 small GEMMs (K=300) fused into one launch
// (outputs feed elementwise consumers / epilogue adds only — no tf32 rounding)
// ---------------------------------------------------------------------------
__global__ void tables_k(const float* __restrict__ enc_emb,
                         const float* __restrict__ dec_emb,
                         const float* __restrict__ Wih_f, const float* __restrict__ bih_f,
                         const float* __restrict__ Wih_b, const float* __restrict__ bih_b,
                         const float* __restrict__ dWih,  const float* __restrict__ dbih,
                         const float* __restrict__ fcW_emb, const float* __restrict__ fcb,
                         float* __restrict__ o0, float* __restrict__ o1,
                         float* __restrict__ o2, float* __restrict__ o3) {
    int idx = blockIdx.x * blockDim.x + threadIdx.x;
    const int J0 = VIN * G3, J1 = 2 * VIN * G3, J2 = J1 + VOUT * G3, J3 = J2 + VOUT * VOUT;
    if (idx >= J3) return;
    const float* A; const float* Bw; const float* bias; float* C;
    int m, n, ldb;
    if (idx < J0)      { int r = idx;      m = r / G3;  n = r % G3;  A = enc_emb; Bw = Wih_f;   bias = bih_f; C = o0 + r; ldb = G3; }
    else if (idx < J1) { int r = idx - J0; m = r / G3;  n = r % G3;  A = enc_emb; Bw = Wih_b;   bias = bih_b; C = o1 + r; ldb = G3; }
    else if (idx < J2) { int r = idx - J1; m = r / G3;  n = r % G3;  A = dec_emb; Bw = dWih;    bias = dbih;  C = o2 + r; ldb = G3; }
    else               { int r = idx - J2; m = r / VOUT; n = r % VOUT; A = dec_emb; Bw = fcW_emb; bias = fcb; C = o3 + r; ldb = VOUT; }
    float s = bias[n];
    const float* Ar = A + (size_t)m * E;
#pragma unroll 4
    for (int k = 0; k < E; k++) s = fmaf(Ar[k], Bw[(size_t)k * ldb + n], s);
    *C = s;
}

// ---------------------------------------------------------------------------
// Fused weight preparation: 6 transposes + bias_cat, all tf32-rounded
// ---------------------------------------------------------------------------
__global__ void prep_k(const float* __restrict__ Whh_f, const float* __restrict__ Whh_b,
                       const float* __restrict__ dWih300,
                       const float* __restrict__ fcW,
                       const float* __restrict__ enc_fcW, const float* __restrict__ attn_We,
                       const float* __restrict__ attn_b, const float* __restrict__ dec_bhh,
                       float* __restrict__ WhhT_f, float* __restrict__ WhhT_b,
                       float* __restrict__ dec_WihT, float* __restrict__ fcWT,
                       float* __restrict__ enc_fcWT, float* __restrict__ attn_WeT,
                       float* __restrict__ bias_cat) {
    int idx = blockIdx.x * blockDim.x + threadIdx.x;
    const int L0 = 256 * 768;
    const int L1 = L0 + 256 * 768;
    const int L2 = L1 + 512 * 768;
    const int L3 = L2 + 768 * 128;
    const int L4 = L3 + 512 * 256;
    const int L5 = L4 + 512 * 256;
    const int L6 = L5 + 1024;
    if (idx >= L6) return;
    if (idx < L0)      { int li = idx;      int r = li / 768, c = li % 768; WhhT_f[(size_t)c * 256 + r] = rnd_tf32(Whh_f[li]); }
    else if (idx < L1) { int li = idx - L0; int r = li / 768, c = li % 768; WhhT_b[(size_t)c * 256 + r] = rnd_tf32(Whh_b[li]); }
    else if (idx < L2) { int li = idx - L1; int r = li / 768, c = li % 768; dec_WihT[(size_t)c * 512 + r] = rnd_tf32(dWih300[li]); }
    else if (idx < L3) { int li = idx - L2; int r = li / 128, c = li % 128; fcWT[(size_t)c * 768 + r] = rnd_tf32(fcW[li]); }
    else if (idx < L4) { int li = idx - L3; int r = li / 256, c = li % 256; enc_fcWT[(size_t)c * 512 + r] = rnd_tf32(enc_fcW[li]); }
    else if (idx < L5) { int li = idx - L4; int r = li / 256, c = li % 256; attn_WeT[(size_t)c * 512 + r] = rnd_tf32(attn_We[li]); }
    else               { int li = idx - L5; bias_cat[li] = (li < H) ? attn_b[li] : dec_bhh[li - H]; }
}

__global__ void build_wcatT(const float* __restrict__ Wh, const float* __restrict__ Whh,
                            float* __restrict__ WcatT) {
    int idx = blockIdx.x * blockDim.x + threadIdx.x;
    if (idx >= 1024 * H) return;
    int n = idx / H, k = idx % H;
    WcatT[idx] = rnd_tf32((n < H) ? Wh[(size_t)k * H + n] : Whh[(size_t)k * G3 + (n - H)]);
}

// ---------------------------------------------------------------------------
// Tensor-core tf32 GEMM, mma.sync m16n8k8 + cp.async 2-stage pipeline.
// Operands must be pre-rounded to tf32 by producers (cp.async copies raw).
// Warp grid WM x WN, warp tile (MT*16) x (NT*8), CTA tile BM x BN, BK=32.
// Smem rows stride 36 floats. blockIdx.z==1 -> second problem.
// ---------------------------------------------------------------------------
template<int WM, int WN, int MT, int NT>
__global__ __launch_bounds__(256, 2)
void gemm_mma(const float* __restrict__ A, int lda,
              const float* __restrict__ Bt,            // [N,K] row-major
              float* __restrict__ C, int ldc,
              int M, int N, int K,
              const float* __restrict__ bias,
              const float* __restrict__ gtab, const int* __restrict__ gidx, int ldgt,
              int act,
              const float* __restrict__ A2, const float* __restrict__ Bt2,
              float* __restrict__ C2, const float* __restrict__ bias2) {
    constexpr int BM  = WM * MT * 16;
    constexpr int BN  = WN * NT * 8;
    constexpr int LA  = BM * 8 / 256;   // float4 cp.async per thread (A)
    constexpr int LB  = BN * 8 / 256;   // float4 cp.async per thread (B)
    constexpr int STG = (BM + BN) * 36; // floats per stage

    if (blockIdx.z == 1) { A = A2; Bt = Bt2; C = C2; bias = bias2; }

    extern __shared__ float sm[];
    const uint32_t sbase = smem_u32(sm);

    const int tid  = threadIdx.x;
    const int lane = tid & 31;
    const int wid  = tid >> 5;
    const int wm   = wid % WM;
    const int wn   = wid / WM;
    const int grp  = lane >> 2;
    const int tig  = lane & 3;
    const int m0   = blockIdx.y * BM;
    const int n0   = blockIdx.x * BN;

    const int arow = tid >> 3;          // 0..31 (x8 rounds below)
    const int k4   = (tid & 7) * 4;     // k offset within 32-chunk

    auto prefetch = [&](int k0, int st) {
        const uint32_t base = sbase + (uint32_t)st * STG * 4;
#pragma unroll
        for (int l = 0; l < LA; l++) {
            int row = arow + l * 32;
            cp_async16(base + (row * 36 + k4) * 4,
                       A + (size_t)(m0 + row) * lda + k0 + k4);
        }
#pragma unroll
        for (int l = 0; l < LB; l++) {
            int row = arow + l * 32;
            cp_async16(base + ((BM + row) * 36 + k4) * 4,
                       Bt + (size_t)(n0 + row) * K + k0 + k4);
        }
        asm volatile("cp.async.commit_group;" ::: "memory");
    };

    float acc[MT][NT][4];
#pragma unroll
    for (int mt = 0; mt < MT; mt++)
#pragma unroll
        for (int nt = 0; nt < NT; nt++)
#pragma unroll
            for (int j = 0; j < 4; j++) acc[mt][nt][j] = 0.0f;

    const int nk = K >> 5;
    prefetch(0, 0);

    for (int kc = 0; kc < nk; kc++) {
        const int cur = kc & 1;
        if (kc + 1 < nk) {
            prefetch((kc + 1) * 32, cur ^ 1);
            asm volatile("cp.async.wait_group 1;" ::: "memory");
        } else {
            asm volatile("cp.async.wait_group 0;" ::: "memory");
        }
        __syncthreads();

        const float* As = sm + cur * STG;
        const float* Bs = As + BM * 36;

#pragma unroll
        for (int ks = 0; ks < 4; ks++) {
            const int kb = ks * 8;
            uint32_t af[MT][4], bf[NT][2];
#pragma unroll
            for (int mt = 0; mt < MT; mt++) {
                const int r = wm * MT * 16 + mt * 16 + grp;
                af[mt][0] = __float_as_uint(As[(r    ) * 36 + kb + tig]);
                af[mt][1] = __float_as_uint(As[(r + 8) * 36 + kb + tig]);
                af[mt][2] = __float_as_uint(As[(r    ) * 36 + kb + tig + 4]);
                af[mt][3] = __float_as_uint(As[(r + 8) * 36 + kb + tig + 4]);
            }
#pragma unroll
            for (int nt = 0; nt < NT; nt++) {
                const int c_ = wn * NT * 8 + nt * 8 + grp;
                bf[nt][0] = __float_as_uint(Bs[c_ * 36 + kb + tig]);
                bf[nt][1] = __float_as_uint(Bs[c_ * 36 + kb + tig + 4]);
            }
#pragma unroll
            for (int mt = 0; mt < MT; mt++)
#pragma unroll
                for (int nt = 0; nt < NT; nt++)
                    asm volatile(
                        "mma.sync.aligned.m16n8k8.row.col.f32.tf32.tf32.f32 "
                        "{%0,%1,%2,%3}, {%4,%5,%6,%7}, {%8,%9}, {%0,%1,%2,%3};"
                        : "+f"(acc[mt][nt][0]), "+f"(acc[mt][nt][1]),
                          "+f"(acc[mt][nt][2]), "+f"(acc[mt][nt][3])
                        : "r"(af[mt][0]), "r"(af[mt][1]), "r"(af[mt][2]), "r"(af[mt][3]),
                          "r"(bf[nt][0]), "r"(bf[nt][1]));
        }
        __syncthreads();
    }

    // epilogue
#pragma unroll
    for (int mt = 0; mt < MT; mt++) {
        const int r0 = m0 + wm * MT * 16 + mt * 16 + grp;
        const int r1 = r0 + 8;
        const float* gr0 = gtab ? (gtab + (size_t)gidx[r0] * ldgt) : nullptr;
        const float* gr1 = gtab ? (gtab + (size_t)gidx[r1] * ldgt) : nullptr;
        float* C0 = C + (size_t)r0 * ldc;
        float* C1 = C + (size_t)r1 * ldc;
#pragma unroll
        for (int nt = 0; nt < NT; nt++) {
            const int n = n0 + wn * NT * 8 + nt * 8 + 2 * tig;
            float v0 = acc[mt][nt][0], v1 = acc[mt][nt][1];
            float v2 = acc[mt][nt][2], v3 = acc[mt][nt][3];
            if (bias) { float b0 = bias[n], b1 = bias[n + 1]; v0 += b0; v1 += b1; v2 += b0; v3 += b1; }
            if (gr0)  { v0 += gr0[n]; v1 += gr0[n + 1]; v2 += gr1[n]; v3 += gr1[n + 1]; }
            if (act == 1) {   // tanh + tf32-round (output feeds a GEMM A operand)
                v0 = rnd_tf32(tanh_acc(v0)); v1 = rnd_tf32(tanh_acc(v1));
                v2 = rnd_tf32(tanh_acc(v2)); v3 = rnd_tf32(tanh_acc(v3));
            }
            *reinterpret_cast<float2*>(C0 + n) = make_float2(v0, v1);
            *reinterpret_cast<float2*>(C1 + n) = make_float2(v2, v3);
        }
    }
}

// ---------------------------------------------------------------------------
// Encoder GRU cell (both directions via blockIdx.z); h written tf32-rounded
// ---------------------------------------------------------------------------
__global__ void enc_cell(const float* __restrict__ gh_f, const float* __restrict__ gh_b,
                         const float* __restrict__ emb_f, const float* __restrict__ emb_b,
                         const int* __restrict__ src, int s,
                         float* __restrict__ hf, float* __restrict__ hb,
                         float* __restrict__ enc_out) {
    int dir = blockIdx.z;
    int idx = blockIdx.x * blockDim.x + threadIdx.x;
    int b = idx >> 8;
    int h = idx & 255;
    int s_in = dir ? (S - 1 - s) : s;
    int tok  = src[s_in * B + b];
    const float* gh = (dir ? gh_b : gh_f) + (size_t)b * G3;
    const float* gi = (dir ? emb_b : emb_f) + (size_t)tok * G3;
    float* hp = (dir ? hb : hf) + (size_t)b * H + h;
    float r = sig_acc(gi[h] + gh[h]);
    float z = sig_acc(gi[H + h] + gh[H + h]);
    float n = tanh_acc(gi[2 * H + h] + r * gh[2 * H + h]);
    float hprev = *hp;
    float hn = rnd_tf32((1.0f - z) * n + z * hprev);
    *hp = hn;
    enc_out[((size_t)b * S + s_in) * H2 + dir * H + h] = hn;
}

// ---------------------------------------------------------------------------
// Decoder GRU cell; h/xcat written tf32-rounded
// ---------------------------------------------------------------------------
__global__ void dec_cell(const float* __restrict__ g1, const float* __restrict__ gi,
                         float* __restrict__ h, float* __restrict__ xcat) {
    int idx = blockIdx.x * blockDim.x + threadIdx.x;
    int b = idx >> 8;
    int hh = idx & 255;
    const float* gh  = g1 + (size_t)b * 1024 + H;
    const float* gip = gi + (size_t)b * G3;
    float r = sig_acc(gip[hh] + gh[hh]);
    float z = sig_acc(gip[H + hh] + gh[H + hh]);
    float n = tanh_acc(gip[2 * H + hh] + r * gh[2 * H + hh]);
    float hprev = h[(size_t)b * H + hh];
    float hn = rnd_tf32((1.0f - z) * n + z * hprev);
    h[(size_t)b * H + hh] = hn;
    xcat[(size_t)b * G3 + hh] = hn;
}

// ---------------------------------------------------------------------------
// Attention: parallel energies (warp-per-s); weighted written tf32-rounded
// ---------------------------------------------------------------------------
__global__ __launch_bounds__(256)
void attn_k(const float* __restrict__ g1, const float* __restrict__ proj,
            const float* __restrict__ enc_out, const float* __restrict__ v,
            float* __restrict__ weighted, float* __restrict__ xcat) {
    const int b   = blockIdx.x;
    const int tid = threadIdx.x;
    const int wid = tid >> 5, lane = tid & 31;
    __shared__ float q_sh[256], v_sh[256], e_sh[S], a_sh[S];

    q_sh[tid] = g1[(size_t)b * 1024 + tid];
    v_sh[tid] = v[tid];
    __syncthreads();

    const float* prow = proj + (size_t)b * S * H;
#pragma unroll
    for (int r = 0; r < 3; r++) {
        const int s = wid + r * 8;
        const float4* p4 = reinterpret_cast<const float4*>(prow + s * H + lane * 8);
        float4 p0 = p4[0], p1 = p4[1];
        float4 q0 = *reinterpret_cast<const float4*>(&q_sh[lane * 8]);
        float4 q1 = *reinterpret_cast<const float4*>(&q_sh[lane * 8 + 4]);
        float4 w0 = *reinterpret_cast<const float4*>(&v_sh[lane * 8]);
        float4 w1 = *reinterpret_cast<const float4*>(&v_sh[lane * 8 + 4]);
        float val = w0.x * tanh_approx(q0.x + p0.x)
                  + w0.y * tanh_approx(q0.y + p0.y)
                  + w0.z * tanh_approx(q0.z + p0.z)
                  + w0.w * tanh_approx(q0.w + p0.w)
                  + w1.x * tanh_approx(q1.x + p1.x)
                  + w1.y * tanh_approx(q1.y + p1.y)
                  + w1.z * tanh_approx(q1.z + p1.z)
                  + w1.w * tanh_approx(q1.w + p1.w);
#pragma unroll
        for (int o = 16; o > 0; o >>= 1) val += __shfl_xor_sync(0xffffffffu, val, o);
        if (lane == 0) e_sh[s] = val;
    }
    __syncthreads();

    if (tid < 32) {
        float x = (tid < S) ? e_sh[tid] : -1e30f;
        float mx = x;
#pragma unroll
        for (int o = 16; o > 0; o >>= 1) mx = fmaxf(mx, __shfl_xor_sync(0xffffffffu, mx, o));
        float ex = (tid < S) ? __expf(x - mx) : 0.0f;
        float sm = ex;
#pragma unroll
        for (int o = 16; o > 0; o >>= 1) sm += __shfl_xor_sync(0xffffffffu, sm, o);
        if (tid < S) a_sh[tid] = __fdividef(ex, sm);
    }
    __syncthreads();

    const float* orow = enc_out + (size_t)b * S * H2;
#pragma unroll
    for (int d = tid; d < H2; d += 256) {
        float acc = 0.0f;
#pragma unroll
        for (int s = 0; s < S; s++) acc = fmaf(a_sh[s], orow[s * H2 + d], acc);
        float av = rnd_tf32(acc);
        weighted[(size_t)b * H2 + d] = av;
        xcat[(size_t)b * G3 + H + d] = av;
    }
}

__global__ void concat_h(const float* __restrict__ hf, const float* __restrict__ hb,
                         float* __restrict__ cat) {
    int idx = blockIdx.x * blockDim.x + threadIdx.x;
    int b = idx >> 9, j = idx & 511;
    cat[idx] = (j < H) ? hf[b * H + j] : hb[b * H + (j - H)];
}

// ---------------------------------------------------------------------------
// Host launch helpers
// ---------------------------------------------------------------------------
constexpr int SMEM_MAIN = 2 * (128 + 64) * 36 * 4;   // 55296 B (BM=128,BN=64)
constexpr int SMEM_LOG  = 2 * (64 + 64) * 36 * 4;    // 36864 B (BM=64, BN=64)

static void gemm_mainL(const float* A, int lda, const float* Bt,
                       float* C, int ldc, int M, int N, int K,
                       const float* bias, const float* gtab, const int* gidx, int ldgt,
                       int act,
                       const float* A2 = nullptr, const float* Bt2 = nullptr,
                       float* C2 = nullptr, const float* bias2 = nullptr) {
    static bool attr_set = false;
    if (!attr_set) {
        cudaFuncSetAttribute(gemm_mma<4, 2, 2, 4>,
                             cudaFuncAttributeMaxDynamicSharedMemorySize, SMEM_MAIN);
        attr_set = true;
    }
    dim3 g(N / 64, M / 128, A2 ? 2 : 1);
    gemm_mma<4, 2, 2, 4><<<g, 256, SMEM_MAIN>>>(A, lda, Bt, C, ldc, M, N, K,
                                                bias, gtab, gidx, ldgt, act,
                                                A2, Bt2, C2, bias2);
}
static void gemm_logL(const float* A, int lda, const float* Bt,
                      float* C, int ldc, int M, int N, int K,
                      const float* bias, const float* gtab, const int* gidx, int ldgt,
                      int act) {
    static bool attr_set = false;
    if (!attr_set) {
        cudaFuncSetAttribute(gemm_mma<2, 4, 2, 2>,
                             cudaFuncAttributeMaxDynamicSharedMemorySize, SMEM_LOG);
        attr_set = true;
    }
    dim3 g(N / 64, M / 64, 1);
    gemm_mma<2, 4, 2, 2><<<g, 256, SMEM_LOG>>>(A, lda, Bt, C, ldc, M, N, K,
                                               bias, gtab, gidx, ldgt, act,
                                               nullptr, nullptr, nullptr, nullptr);
}

extern "C" void kernel_launch(void* const* d_in, const int* in_sizes, int n_in,
                              void* d_out, int out_size) {
    const int*   src       = (const int*)  d_in[0];
    const int*   trg       = (const int*)  d_in[1];
    const float* enc_emb   = (const float*)d_in[2];
    const float* enc_Wih_f = (const float*)d_in[3];
    const float* enc_Whh_f = (const float*)d_in[4];
    const float* enc_bih_f = (const float*)d_in[5];
    const float* enc_bhh_f = (const float*)d_in[6];
    const float* enc_Wih_b = (const float*)d_in[7];
    const float* enc_Whh_b = (const float*)d_in[8];
    const float* enc_bih_b = (const float*)d_in[9];
    const float* enc_bhh_b = (const float*)d_in[10];
    const float* enc_fcW   = (const float*)d_in[11];
    const float* enc_fcb   = (const float*)d_in[12];
    const float* attn_Wh   = (const float*)d_in[13];
    const float* attn_We   = (const float*)d_in[14];
    const float* attn_b    = (const float*)d_in[15];
    const float* attn_v    = (const float*)d_in[16];
    const float* dec_emb   = (const float*)d_in[17];
    const float* dec_Wih   = (const float*)d_in[18];
    const float* dec_Whh   = (const float*)d_in[19];
    const float* dec_bih   = (const float*)d_in[20];
    const float* dec_bhh   = (const float*)d_in[21];
    const float* fcW       = (const float*)d_in[22];
    const float* fcb       = (const float*)d_in[23];
    float* out = (float*)d_out;

    float *p_emb_gi_f, *p_emb_gi_b, *p_dec_gi_emb, *p_dec_logit_emb;
    float *p_bias_cat, *p_hf, *p_hb, *p_h, *p_cat512;
    float *p_enc_out, *p_enc_proj, *p_gh, *p_g1, *p_gi, *p_weighted, *p_xcat;
    float *p_WhhT_f, *p_WhhT_b, *p_WcatT, *p_dec_WihT, *p_fcWT, *p_enc_fcWT, *p_attn_WeT;
    void* tmp;
    cudaGetSymbolAddress(&tmp, g_emb_gi_f);      p_emb_gi_f     = (float*)tmp;
    cudaGetSymbolAddress(&tmp, g_emb_gi_b);      p_emb_gi_b     = (float*)tmp;
    cudaGetSymbolAddress(&tmp, g_dec_gi_emb);    p_dec_gi_emb   = (float*)tmp;
    cudaGetSymbolAddress(&tmp, g_dec_logit_emb); p_dec_logit_emb= (float*)tmp;
    cudaGetSymbolAddress(&tmp, g_bias_cat);      p_bias_cat     = (float*)tmp;
    cudaGetSymbolAddress(&tmp, g_hf);            p_hf           = (float*)tmp;
    cudaGetSymbolAddress(&tmp, g_hb);            p_hb           = (float*)tmp;
    cudaGetSymbolAddress(&tmp, g_h);             p_h            = (float*)tmp;
    cudaGetSymbolAddress(&tmp, g_cat512);        p_cat512       = (float*)tmp;
    cudaGetSymbolAddress(&tmp, g_enc_out);       p_enc_out      = (float*)tmp;
    cudaGetSymbolAddress(&tmp, g_enc_proj);      p_enc_proj     = (float*)tmp;
    cudaGetSymbolAddress(&tmp, g_gh);            p_gh           = (float*)tmp;
    cudaGetSymbolAddress(&tmp, g_g1);            p_g1           = (float*)tmp;
    cudaGetSymbolAddress(&tmp, g_gi);            p_gi           = (float*)tmp;
    cudaGetSymbolAddress(&tmp, g_weighted);      p_weighted     = (float*)tmp;
    cudaGetSymbolAddress(&tmp, g_xcat);          p_xcat         = (float*)tmp;
    cudaGetSymbolAddress(&tmp, g_WhhT_f);        p_WhhT_f       = (float*)tmp;
    cudaGetSymbolAddress(&tmp, g_WhhT_b);        p_WhhT_b       = (float*)tmp;
    cudaGetSymbolAddress(&tmp, g_WcatT);         p_WcatT        = (float*)tmp;
    cudaGetSymbolAddress(&tmp, g_dec_WihT);      p_dec_WihT     = (float*)tmp;
    cudaGetSymbolAddress(&tmp, g_fcWT);          p_fcWT         = (float*)tmp;
    cudaGetSymbolAddress(&tmp, g_enc_fcWT);      p_enc_fcWT     = (float*)tmp;
    cudaGetSymbolAddress(&tmp, g_attn_WeT);      p_attn_WeT     = (float*)tmp;

    // ---- precompute: tables + fused weight prep ----
    {
        int total = 2 * VIN * G3 + VOUT * G3 + VOUT * VOUT;
        tables_k<<<(total + 255) / 256, 256>>>(enc_emb, dec_emb,
                                               enc_Wih_f, enc_bih_f,
                                               enc_Wih_b, enc_bih_b,
                                               dec_Wih, dec_bih,
                                               fcW + (size_t)G3 * VOUT, fcb,
                                               p_emb_gi_f, p_emb_gi_b,
                                               p_dec_gi_emb, p_dec_logit_emb);
    }
    {
        const int L6 = 2 * 256 * 768 + 512 * 768 + 768 * 128 + 2 * 512 * 256 + 1024;
        prep_k<<<(L6 + 255) / 256, 256>>>(enc_Whh_f, enc_Whh_b,
                                          dec_Wih + (size_t)E * G3, fcW,
                                          enc_fcW, attn_We, attn_b, dec_bhh,
                                          p_WhhT_f, p_WhhT_b, p_dec_WihT, p_fcWT,
                                          p_enc_fcWT, p_attn_WeT, p_bias_cat);
        build_wcatT<<<(1024 * H + 255) / 256, 256>>>(attn_Wh, dec_Whh, p_WcatT);
    }
    cudaMemsetAsync(p_hf, 0, (size_t)B * H * sizeof(float));
    cudaMemsetAsync(p_hb, 0, (size_t)B * H * sizeof(float));
    cudaMemsetAsync(out, 0, (size_t)B * VOUT * sizeof(float));

    // ---- encoder: 24 steps, fwd+bwd fused via grid.z ----
    for (int s = 0; s < S; s++) {
        gemm_mainL(p_hf, H, p_WhhT_f, p_gh, G3, B, G3, H,
                   enc_bhh_f, nullptr, nullptr, 0, 0,
                   p_hb, p_WhhT_b, p_gh + (size_t)B * G3, enc_bhh_b);
        enc_cell<<<dim3(B * H / 256, 1, 2), 256>>>(p_gh, p_gh + (size_t)B * G3,
                                                   p_emb_gi_f, p_emb_gi_b,
                                                   src, s, p_hf, p_hb, p_enc_out);
    }

    // ---- decoder init hidden = tanh([hf|hb] @ enc_fcW + enc_fcb) ----
    concat_h<<<B * H2 / 256, 256>>>(p_hf, p_hb, p_cat512);
    gemm_mainL(p_cat512, H2, p_enc_fcWT, p_h, H, B, H, H2,
               enc_fcb, nullptr, nullptr, 0, /*tanh+rnd*/1);

    // ---- enc_proj = enc_out @ attn_We ----
    gemm_mainL(p_enc_out, H2, p_attn_WeT, p_enc_proj, H, B * S, H, H2,
               nullptr, nullptr, nullptr, 0, 0);

    // ---- decoder: 24 steps ----
    for (int t = 0; t < T - 1; t++) {
        const int* tok = trg + t * B;
        gemm_mainL(p_h, H, p_WcatT, p_g1, 1024, B, 1024, H,
                   p_bias_cat, nullptr, nullptr, 0, 0);
        attn_k<<<B, 256>>>(p_g1, p_enc_proj, p_enc_out, attn_v, p_weighted, p_xcat);
        gemm_mainL(p_weighted, H2, p_dec_WihT, p_gi, G3, B, G3, H2,
                   nullptr, p_dec_gi_emb, tok, G3, 0);
        dec_cell<<<B * H / 256, 256>>>(p_g1, p_gi, p_h, p_xcat);
        gemm_logL(p_xcat, G3, p_fcWT, out + (size_t)(t + 1) * B * VOUT, VOUT,
                  B, VOUT, G3, nullptr, p_dec_logit_emb, tok, VOUT, 0);
    }
}